// round 14
// baseline (speedup 1.0000x reference)
#include <cuda_runtime.h>
#include <cstdint>

#define FD 1024
#define RD 64
#define MT 128
#define NCH 16          // GEMM1 chunks of 64 cols

// ---------------- device scratch ----------------
__device__ float g_Gp[8][RD * RD];      // partial Gram matrices
__device__ uint4 g_PP[64 * 8 * 32];     // GEMM1 B frags (P, contraction over f)
__device__ uint4 g_PT[128 * 4 * 32];    // GEMM2 B frags (P, contraction over r, f-permuted)
__device__ uint4 g_MP[8 * 4 * 32];      // d3 B frags (G^-1)
__device__ int   g_flag_inv;

// ---------------- helpers ----------------
__device__ __forceinline__ void split2(float x, float y, uint32_t& hi, uint32_t& lo) {
    asm("cvt.rn.bf16x2.f32 %0, %1, %2;" : "=r"(hi) : "f"(y), "f"(x));
    float xr = x - __uint_as_float(hi << 16);
    float yr = y - __uint_as_float(hi & 0xffff0000u);
    asm("cvt.rn.bf16x2.f32 %0, %1, %2;" : "=r"(lo) : "f"(yr), "f"(xr));
}

__device__ __forceinline__ void mma_bf16(float* d,
    uint32_t a0, uint32_t a1, uint32_t a2, uint32_t a3,
    uint32_t b0, uint32_t b1) {
    asm volatile("mma.sync.aligned.m16n8k16.row.col.f32.bf16.bf16.f32 "
        "{%0,%1,%2,%3}, {%4,%5,%6,%7}, {%8,%9}, {%0,%1,%2,%3};"
        : "+f"(d[0]), "+f"(d[1]), "+f"(d[2]), "+f"(d[3])
        : "r"(a0), "r"(a1), "r"(a2), "r"(a3), "r"(b0), "r"(b1));
}

__device__ __forceinline__ void cpa16(uint32_t s, const void* g) {
    asm volatile("cp.async.cg.shared.global [%0], [%1], 16;" :: "r"(s), "l"(g));
}
#define CP_COMMIT asm volatile("cp.async.commit_group;" ::: "memory")
#define CP_WAIT0  asm volatile("cp.async.wait_group 0;" ::: "memory")

// ---------------- prep: partial gram (blocks 0-7) + pack P both ways (all 64) ----------------
__global__ void k_prep1(const float* __restrict__ probe) {
    __shared__ float Ps[128][68];
    int t = threadIdx.x;
    if (blockIdx.x == 0 && t == 0) g_flag_inv = 0;
    if (blockIdx.x < 8) {
        int c = blockIdx.x;
        #pragma unroll
        for (int i = 0; i < 8; i++) {
            int idx = t + 256 * i;
            int fl = idx >> 4, r4 = (idx & 15) << 2;
            float4 v = *(const float4*)(probe + (c * 128 + fl) * 64 + r4);
            *(float4*)(&Ps[fl][r4]) = v;
        }
        __syncthreads();
        int ti = (t >> 4) << 2, tj = (t & 15) << 2;
        float acc[4][4];
        #pragma unroll
        for (int a = 0; a < 4; a++)
            #pragma unroll
            for (int b = 0; b < 4; b++) acc[a][b] = 0.f;
        for (int k = 0; k < 128; k++) {
            float av[4], bv[4];
            #pragma unroll
            for (int a = 0; a < 4; a++) av[a] = Ps[k][ti + a];
            #pragma unroll
            for (int b = 0; b < 4; b++) bv[b] = Ps[k][tj + b];
            #pragma unroll
            for (int a = 0; a < 4; a++)
                #pragma unroll
                for (int b = 0; b < 4; b++) acc[a][b] = fmaf(av[a], bv[b], acc[a][b]);
        }
        #pragma unroll
        for (int a = 0; a < 4; a++)
            #pragma unroll
            for (int b = 0; b < 4; b++)
                g_Gp[c][(ti + a) * 64 + tj + b] = acc[a][b];
    }
    // pack g_PP: GEMM1 B, k-slot permutation 16kk+4tq+{0,1}/{2,3}
    {
        int id = blockIdx.x * 256 + t;
        int lane = id & 31, g = lane >> 2, tq = lane & 3;
        int kk = id >> 8, j = (id >> 5) & 7;
        int n = 8 * j + g, k0 = 16 * kk + 4 * tq;
        float p00 = probe[(k0) * 64 + n],     p01 = probe[(k0 + 1) * 64 + n];
        float p10 = probe[(k0 + 2) * 64 + n], p11 = probe[(k0 + 3) * 64 + n];
        uint32_t h0, l0, h1, l1;
        split2(p00, p01, h0, l0);
        split2(p10, p11, h1, l1);
        g_PP[id] = make_uint4(h0, h1, l0, l1);
    }
    // pack g_PT: GEMM2 B (contraction over r), f-permuted for float4 epilogue
    {
        int id = blockIdx.x * 256 + t;
        int lane = id & 31, g = lane >> 2, tq = lane & 3;
        int T = id >> 7, kk = (id >> 5) & 3;
        int f = 16 * (T >> 1) + 4 * (g >> 1) + 2 * (T & 1) + (g & 1);
        int r0 = 16 * kk + 2 * tq;
        float w00 = probe[f * 64 + r0],     w01 = probe[f * 64 + r0 + 1];
        float w10 = probe[f * 64 + r0 + 8], w11 = probe[f * 64 + r0 + 9];
        uint32_t h0, l0, h1, l1;
        split2(w00, w01, h0, l0);
        split2(w10, w11, h1, l1);
        g_PT[id] = make_uint4(h0, h1, l0, l1);
    }
}

// ---------------- main kernel ----------------
// words [0,8192): GEMM1 B double-buffer / GEMM2 buf0
// words [8192,16448): block-0 GJ (64x129) -> later GEMM2 buf1
#define SMEM_WORDS 16448
#define SMEM_BYTES (SMEM_WORDS * 4)

__global__ void __launch_bounds__(256, 2)
k_main(const float* __restrict__ hs, float* __restrict__ out) {
    extern __shared__ uint32_t smw[];
    uint4* Bs = (uint4*)smw;

    const int t = threadIdx.x;
    const int wg = t >> 5, lane = t & 31, g = lane >> 2, tq = lane & 3;
    const size_t g0 = (size_t)blockIdx.x * MT;
    const size_t rowA = g0 + 16 * wg + g, rowB = rowA + 8;
    const float* hA = hs + rowA * FD;
    const float* hB = hs + rowB * FD;

    uint32_t sbase = (uint32_t)__cvta_generic_to_shared(smw);

    // ======== block 0 ONLY: Gauss-Jordan inverse -> g_MP + release flag ========
    if (blockIdx.x == 0) {
        float* A = (float*)(smw + 8192);        // 64 x 129
        const int r = t >> 2, cs = t & 3;
        const int col0 = cs * 32;
        if (cs < 2) {
            #pragma unroll
            for (int i = 0; i < 8; i++) {
                float4 s = make_float4(0.f, 0.f, 0.f, 0.f);
                #pragma unroll
                for (int p = 0; p < 8; p++) {
                    float4 v = *(const float4*)(g_Gp[p] + r * 64 + col0 + 4 * i);
                    s.x += v.x; s.y += v.y; s.z += v.z; s.w += v.w;
                }
                A[r * 129 + col0 + 4 * i + 0] = s.x;
                A[r * 129 + col0 + 4 * i + 1] = s.y;
                A[r * 129 + col0 + 4 * i + 2] = s.z;
                A[r * 129 + col0 + 4 * i + 3] = s.w;
            }
        } else {
            #pragma unroll 8
            for (int i = 0; i < 32; i++)
                A[r * 129 + col0 + i] = ((col0 + i - 64) == r) ? 1.f : 0.f;
        }
        __syncthreads();
        for (int k = 0; k < 64; k++) {
            float inv = 1.f / A[k * 129 + k];
            float f = A[r * 129 + k];
            if (r == k) {
                #pragma unroll 8
                for (int i = 0; i < 32; i++) A[k * 129 + col0 + i] *= inv;
            }
            __syncthreads();
            if (r != k) {
                #pragma unroll 8
                for (int i = 0; i < 32; i++)
                    A[r * 129 + col0 + i] = fmaf(-f, A[k * 129 + col0 + i], A[r * 129 + col0 + i]);
            }
            __syncthreads();
        }
        // pack g_MP (4 uint4 per thread)
        #pragma unroll
        for (int i = 0; i < 4; i++) {
            int id = t + 256 * i;
            int ln = id & 31, gg = ln >> 2, tb = ln & 3;
            int j = id >> 7, kk = (id >> 5) & 3;
            int n = 8 * j + gg, k0 = 16 * kk + 2 * tb;
            float m00 = A[k0 * 129 + 64 + n],       m01 = A[(k0 + 1) * 129 + 64 + n];
            float m10 = A[(k0 + 8) * 129 + 64 + n], m11 = A[(k0 + 9) * 129 + 64 + n];
            uint32_t h0, l0, h1, l1;
            split2(m00, m01, h0, l0);
            split2(m10, m11, h1, l1);
            g_MP[id] = make_uint4(h0, h1, l0, l1);
        }
        __threadfence();
        __syncthreads();
        if (t == 0) atomicExch(&g_flag_inv, 1);
    }

    // prologue: stage GEMM1 B chunk 0 -> buf0
    #pragma unroll
    for (int q = 0; q < 4; q++)
        cpa16(sbase + (t + 256 * q) * 16, g_PP + t + 256 * q);
    CP_COMMIT;

    float acc1[8][4];
    #pragma unroll
    for (int j = 0; j < 8; j++)
        #pragma unroll
        for (int q = 0; q < 4; q++) acc1[j][q] = 0.f;
    float sqA = 0.f, sqB = 0.f;

    float4 pa[4], pb[4];
    #pragma unroll
    for (int kk = 0; kk < 4; kk++) {
        int c0 = 16 * kk + 4 * tq;
        pa[kk] = *(const float4*)(hA + c0);
        pb[kk] = *(const float4*)(hB + c0);
    }

    // ======== GEMM1: acc1 = H * P, K = 1024 (3-term split) ========
    for (int ch = 0; ch < NCH; ch++) {
        CP_WAIT0;
        __syncthreads();
        const int buf = ch & 1;
        if (ch + 1 < NCH) {
            const uint4* src = g_PP + (ch + 1) * 1024;
            #pragma unroll
            for (int q = 0; q < 4; q++)
                cpa16(sbase + (((buf ^ 1) * 1024 + t + 256 * q) * 16), src + t + 256 * q);
            CP_COMMIT;
        }
        uint32_t ah[4][4], al[4][4];
        #pragma unroll
        for (int kk = 0; kk < 4; kk++) {
            float4 a4 = pa[kk], b4 = pb[kk];
            sqA = fmaf(a4.x, a4.x, fmaf(a4.y, a4.y, fmaf(a4.z, a4.z, fmaf(a4.w, a4.w, sqA))));
            sqB = fmaf(b4.x, b4.x, fmaf(b4.y, b4.y, fmaf(b4.z, b4.z, fmaf(b4.w, b4.w, sqB))));
            split2(a4.x, a4.y, ah[kk][0], al[kk][0]);
            split2(b4.x, b4.y, ah[kk][1], al[kk][1]);
            split2(a4.z, a4.w, ah[kk][2], al[kk][2]);
            split2(b4.z, b4.w, ah[kk][3], al[kk][3]);
        }
        if (ch + 1 < NCH) {
            const int cb = (ch + 1) * 64 + 4 * tq;
            #pragma unroll
            for (int kk = 0; kk < 4; kk++) {
                int c0 = cb + 16 * kk;
                pa[kk] = *(const float4*)(hA + c0);
                pb[kk] = *(const float4*)(hB + c0);
            }
        }
        #pragma unroll
        for (int kk = 0; kk < 4; kk++)
            #pragma unroll
            for (int j = 0; j < 8; j += 2) {
                uint4 b0 = Bs[buf * 1024 + (kk * 8 + j) * 32 + lane];
                uint4 b1 = Bs[buf * 1024 + (kk * 8 + j + 1) * 32 + lane];
                mma_bf16(acc1[j],     ah[kk][0], ah[kk][1], ah[kk][2], ah[kk][3], b0.x, b0.y);
                mma_bf16(acc1[j + 1], ah[kk][0], ah[kk][1], ah[kk][2], ah[kk][3], b1.x, b1.y);
                mma_bf16(acc1[j],     ah[kk][0], ah[kk][1], ah[kk][2], ah[kk][3], b0.z, b0.w);
                mma_bf16(acc1[j + 1], ah[kk][0], ah[kk][1], ah[kk][2], ah[kk][3], b1.z, b1.w);
                mma_bf16(acc1[j],     al[kk][0], al[kk][1], al[kk][2], al[kk][3], b0.x, b0.y);
                mma_bf16(acc1[j + 1], al[kk][0], al[kk][1], al[kk][2], al[kk][3], b1.x, b1.y);
            }
    }

    sqA += __shfl_xor_sync(~0u, sqA, 1); sqA += __shfl_xor_sync(~0u, sqA, 2);
    sqB += __shfl_xor_sync(~0u, sqB, 1); sqB += __shfl_xor_sync(~0u, sqB, 2);

    __syncthreads();   // all warps done with GEMM1 Bs

    // prologue: stage GEMM2 P chunk 0 -> buf0 (2048 uint4)
    #pragma unroll
    for (int q = 0; q < 8; q++)
        cpa16(sbase + (t + 256 * q) * 16, g_PT + t + 256 * q);
    CP_COMMIT;

    // ---- repack acc1 (b) into A frags ----
    uint32_t a2h[4][4], a2l[4][4];
    #pragma unroll
    for (int kk = 0; kk < 4; kk++) {
        split2(acc1[2 * kk][0],     acc1[2 * kk][1],     a2h[kk][0], a2l[kk][0]);
        split2(acc1[2 * kk][2],     acc1[2 * kk][3],     a2h[kk][1], a2l[kk][1]);
        split2(acc1[2 * kk + 1][0], acc1[2 * kk + 1][1], a2h[kk][2], a2l[kk][2]);
        split2(acc1[2 * kk + 1][2], acc1[2 * kk + 1][3], a2h[kk][3], a2l[kk][3]);
    }

    // ---- wait for block-0 GJ (expected zero wait: GJ ~12us, GEMM1 ~45us) ----
    if (t == 0) { while (atomicAdd(&g_flag_inv, 0) == 0) __nanosleep(32); }
    __syncthreads();

    // ---- c = b * G^-1 (g_MP, L2-hot); dot = b.c; repack c into A frags ----
    uint32_t a2ch[4][4], a2cl[4][4];
    float dA = 0.f, dB = 0.f;
    #pragma unroll
    for (int jh = 0; jh < 2; jh++) {
        float accd[4][4];
        #pragma unroll
        for (int j = 0; j < 4; j++)
            #pragma unroll
            for (int q = 0; q < 4; q++) accd[j][q] = 0.f;
        #pragma unroll
        for (int kk = 0; kk < 4; kk++)
            #pragma unroll
            for (int j = 0; j < 4; j += 2) {
                uint4 b0 = g_MP[((jh * 4 + j) * 4 + kk) * 32 + lane];
                uint4 b1 = g_MP[((jh * 4 + j + 1) * 4 + kk) * 32 + lane];
                mma_bf16(accd[j],     a2h[kk][0], a2h[kk][1], a2h[kk][2], a2h[kk][3], b0.x, b0.y);
                mma_bf16(accd[j + 1], a2h[kk][0], a2h[kk][1], a2h[kk][2], a2h[kk][3], b1.x, b1.y);
                mma_bf16(accd[j],     a2h[kk][0], a2h[kk][1], a2h[kk][2], a2h[kk][3], b0.z, b0.w);
                mma_bf16(accd[j + 1], a2h[kk][0], a2h[kk][1], a2h[kk][2], a2h[kk][3], b1.z, b1.w);
                mma_bf16(accd[j],     a2l[kk][0], a2l[kk][1], a2l[kk][2], a2l[kk][3], b0.x, b0.y);
                mma_bf16(accd[j + 1], a2l[kk][0], a2l[kk][1], a2l[kk][2], a2l[kk][3], b1.x, b1.y);
            }
        #pragma unroll
        for (int j = 0; j < 4; j++) {
            int jj = jh * 4 + j;
            dA = fmaf(acc1[jj][0], accd[j][0], dA); dA = fmaf(acc1[jj][1], accd[j][1], dA);
            dB = fmaf(acc1[jj][2], accd[j][2], dB); dB = fmaf(acc1[jj][3], accd[j][3], dB);
        }
        split2(accd[0][0], accd[0][1], a2ch[2 * jh][0], a2cl[2 * jh][0]);
        split2(accd[0][2], accd[0][3], a2ch[2 * jh][1], a2cl[2 * jh][1]);
        split2(accd[1][0], accd[1][1], a2ch[2 * jh][2], a2cl[2 * jh][2]);
        split2(accd[1][2], accd[1][3], a2ch[2 * jh][3], a2cl[2 * jh][3]);
        split2(accd[2][0], accd[2][1], a2ch[2 * jh + 1][0], a2cl[2 * jh + 1][0]);
        split2(accd[2][2], accd[2][3], a2ch[2 * jh + 1][1], a2cl[2 * jh + 1][1]);
        split2(accd[3][0], accd[3][1], a2ch[2 * jh + 1][2], a2cl[2 * jh + 1][2]);
        split2(accd[3][2], accd[3][3], a2ch[2 * jh + 1][3], a2cl[2 * jh + 1][3]);
    }
    dA += __shfl_xor_sync(~0u, dA, 1); dA += __shfl_xor_sync(~0u, dA, 2);
    dB += __shfl_xor_sync(~0u, dB, 1); dB += __shfl_xor_sync(~0u, dB, 2);
    const float scA = sqrtf(sqA / fmaxf(sqA - dA, sqA * 1e-12f));
    const float scB = sqrtf(sqB / fmaxf(sqB - dB, sqB * 1e-12f));

    // ======== GEMM2 + fused epilogue: out = (H - c*Pt) * scale ========
    float* pA = out + rowA * FD;
    float* pB = out + rowB * FD;
    const bool fA = ((rowA & 4095) == 0);
    const bool fB = ((rowB & 4095) == 0);

    for (int nc = 0; nc < 8; nc++) {
        CP_WAIT0;
        __syncthreads();
        const int buf = nc & 1;
        if (nc + 1 < 8) {
            const uint4* src = g_PT + (nc + 1) * 2048;
            #pragma unroll
            for (int q = 0; q < 8; q++)
                cpa16(sbase + (((buf ^ 1) * 2048 + t + 256 * q) * 16), src + t + 256 * q);
            CP_COMMIT;
        }
        #pragma unroll
        for (int half = 0; half < 2; half++) {
            float4 hv0[4], hv1[4];
            #pragma unroll
            for (int p = 0; p < 4; p++) {
                int col = nc * 128 + half * 64 + 16 * p + 4 * tq;
                hv0[p] = *(const float4*)(hA + col);
                hv1[p] = *(const float4*)(hB + col);
            }
            float acc2[8][4];
            #pragma unroll
            for (int jl = 0; jl < 8; jl++)
                #pragma unroll
                for (int q = 0; q < 4; q++) acc2[jl][q] = 0.f;
            #pragma unroll
            for (int kk = 0; kk < 4; kk++)
                #pragma unroll
                for (int jl = 0; jl < 8; jl += 2) {
                    uint4 b0 = Bs[buf * 2048 + ((half * 8 + jl) * 4 + kk) * 32 + lane];
                    uint4 b1 = Bs[buf * 2048 + ((half * 8 + jl + 1) * 4 + kk) * 32 + lane];
                    mma_bf16(acc2[jl],     a2ch[kk][0], a2ch[kk][1], a2ch[kk][2], a2ch[kk][3], b0.x, b0.y);
                    mma_bf16(acc2[jl + 1], a2ch[kk][0], a2ch[kk][1], a2ch[kk][2], a2ch[kk][3], b1.x, b1.y);
                    mma_bf16(acc2[jl],     a2ch[kk][0], a2ch[kk][1], a2ch[kk][2], a2ch[kk][3], b0.z, b0.w);
                    mma_bf16(acc2[jl + 1], a2ch[kk][0], a2ch[kk][1], a2ch[kk][2], a2ch[kk][3], b1.z, b1.w);
                    mma_bf16(acc2[jl],     a2cl[kk][0], a2cl[kk][1], a2cl[kk][2], a2cl[kk][3], b0.x, b0.y);
                    mma_bf16(acc2[jl + 1], a2cl[kk][0], a2cl[kk][1], a2cl[kk][2], a2cl[kk][3], b1.x, b1.y);
                }
            #pragma unroll
            for (int p = 0; p < 4; p++) {
                int col = nc * 128 + half * 64 + 16 * p + 4 * tq;
                float4 o0, o1;
                o0.x = (hv0[p].x - acc2[2 * p][0]) * scA;
                o0.y = (hv0[p].y - acc2[2 * p][1]) * scA;
                o0.z = (hv0[p].z - acc2[2 * p + 1][0]) * scA;
                o0.w = (hv0[p].w - acc2[2 * p + 1][1]) * scA;
                o1.x = (hv1[p].x - acc2[2 * p][2]) * scB;
                o1.y = (hv1[p].y - acc2[2 * p][3]) * scB;
                o1.z = (hv1[p].z - acc2[2 * p + 1][2]) * scB;
                o1.w = (hv1[p].w - acc2[2 * p + 1][3]) * scB;
                if (fA) o0 = hv0[p];
                if (fB) o1 = hv1[p];
                __stcs((float4*)(pA + col), o0);
                __stcs((float4*)(pB + col), o1);
            }
        }
    }
}

extern "C" void kernel_launch(void* const* d_in, const int* in_sizes, int n_in,
                              void* d_out, int out_size) {
    const float* hs = (const float*)d_in[0];
    const float* probe = (const float*)d_in[1];
    float* out = (float*)d_out;

    k_prep1<<<64, 256>>>(probe);

    cudaFuncSetAttribute(k_main, cudaFuncAttributeMaxDynamicSharedMemorySize, SMEM_BYTES);
    int rows = in_sizes[0] / FD;            // 32768
    k_main<<<rows / MT, 256, SMEM_BYTES>>>(hs, out);
}

// round 15
// speedup vs baseline: 1.4255x; 1.4255x over previous
#include <cuda_runtime.h>
#include <cstdint>

#define FD 1024
#define RD 64
#define MT 128
#define NCH 16          // GEMM1 chunks of 64 cols

// ---------------- device scratch ----------------
__device__ float g_Gp[8][RD * RD];      // partial Gram matrices
__device__ uint4 g_PP[64 * 8 * 32];     // GEMM1 B frags (P, contraction over f)
__device__ uint4 g_PT[128 * 4 * 32];    // GEMM2 B frags (P, contraction over r, f-permuted)
__device__ uint4 g_MP[8 * 4 * 32];      // d3 B frags (G^-1)

// ---------------- helpers ----------------
__device__ __forceinline__ void split2(float x, float y, uint32_t& hi, uint32_t& lo) {
    asm("cvt.rn.bf16x2.f32 %0, %1, %2;" : "=r"(hi) : "f"(y), "f"(x));
    float xr = x - __uint_as_float(hi << 16);
    float yr = y - __uint_as_float(hi & 0xffff0000u);
    asm("cvt.rn.bf16x2.f32 %0, %1, %2;" : "=r"(lo) : "f"(yr), "f"(xr));
}

__device__ __forceinline__ void mma_bf16(float* d,
    uint32_t a0, uint32_t a1, uint32_t a2, uint32_t a3,
    uint32_t b0, uint32_t b1) {
    asm volatile("mma.sync.aligned.m16n8k16.row.col.f32.bf16.bf16.f32 "
        "{%0,%1,%2,%3}, {%4,%5,%6,%7}, {%8,%9}, {%0,%1,%2,%3};"
        : "+f"(d[0]), "+f"(d[1]), "+f"(d[2]), "+f"(d[3])
        : "r"(a0), "r"(a1), "r"(a2), "r"(a3), "r"(b0), "r"(b1));
}

__device__ __forceinline__ void cpa16(uint32_t s, const void* g) {
    asm volatile("cp.async.cg.shared.global [%0], [%1], 16;" :: "r"(s), "l"(g));
}
#define CP_COMMIT asm volatile("cp.async.commit_group;" ::: "memory")
#define CP_WAIT0  asm volatile("cp.async.wait_group 0;" ::: "memory")

// ---------------- prep 1: partial gram (blocks 0-7) + pack P both ways (all 64) ----------------
__global__ void k_prep1(const float* __restrict__ probe) {
    __shared__ float Ps[128][68];
    int t = threadIdx.x;
    if (blockIdx.x < 8) {
        int c = blockIdx.x;
        #pragma unroll
        for (int i = 0; i < 8; i++) {
            int idx = t + 256 * i;
            int fl = idx >> 4, r4 = (idx & 15) << 2;
            float4 v = *(const float4*)(probe + (c * 128 + fl) * 64 + r4);
            *(float4*)(&Ps[fl][r4]) = v;
        }
        __syncthreads();
        int ti = (t >> 4) << 2, tj = (t & 15) << 2;
        float acc[4][4];
        #pragma unroll
        for (int a = 0; a < 4; a++)
            #pragma unroll
            for (int b = 0; b < 4; b++) acc[a][b] = 0.f;
        for (int k = 0; k < 128; k++) {
            float av[4], bv[4];
            #pragma unroll
            for (int a = 0; a < 4; a++) av[a] = Ps[k][ti + a];
            #pragma unroll
            for (int b = 0; b < 4; b++) bv[b] = Ps[k][tj + b];
            #pragma unroll
            for (int a = 0; a < 4; a++)
                #pragma unroll
                for (int b = 0; b < 4; b++) acc[a][b] = fmaf(av[a], bv[b], acc[a][b]);
        }
        #pragma unroll
        for (int a = 0; a < 4; a++)
            #pragma unroll
            for (int b = 0; b < 4; b++)
                g_Gp[c][(ti + a) * 64 + tj + b] = acc[a][b];
    }
    // pack g_PP: GEMM1 B, k-slot permutation 16kk+4tq+{0,1}/{2,3}
    {
        int id = blockIdx.x * 256 + t;
        int lane = id & 31, g = lane >> 2, tq = lane & 3;
        int kk = id >> 8, j = (id >> 5) & 7;
        int n = 8 * j + g, k0 = 16 * kk + 4 * tq;
        float p00 = probe[(k0) * 64 + n],     p01 = probe[(k0 + 1) * 64 + n];
        float p10 = probe[(k0 + 2) * 64 + n], p11 = probe[(k0 + 3) * 64 + n];
        uint32_t h0, l0, h1, l1;
        split2(p00, p01, h0, l0);
        split2(p10, p11, h1, l1);
        g_PP[id] = make_uint4(h0, h1, l0, l1);
    }
    // pack g_PT: GEMM2 B (contraction over r), f-permuted for float4 epilogue
    {
        int id = blockIdx.x * 256 + t;
        int lane = id & 31, g = lane >> 2, tq = lane & 3;
        int T = id >> 7, kk = (id >> 5) & 3;
        int f = 16 * (T >> 1) + 4 * (g >> 1) + 2 * (T & 1) + (g & 1);
        int r0 = 16 * kk + 2 * tq;
        float w00 = probe[f * 64 + r0],     w01 = probe[f * 64 + r0 + 1];
        float w10 = probe[f * 64 + r0 + 8], w11 = probe[f * 64 + r0 + 9];
        uint32_t h0, l0, h1, l1;
        split2(w00, w01, h0, l0);
        split2(w10, w11, h1, l1);
        g_PT[id] = make_uint4(h0, h1, l0, l1);
    }
}

// ---------------- prep 2: Gauss-Jordan, grid=148 to defeat the low-grid issue throttle ----------------
// Only block 0 works; blocks 1..147 exist solely to lift the grid above the
// single-CTA throttle threshold (B300: pSmIssueThrottleCtrl vanishes @grid>=148).
__global__ void k_inv() {
    if (blockIdx.x != 0) return;
    __shared__ float A[64 * 129];
    int t = threadIdx.x;                   // 1024
    int r = t >> 4, cs = t & 15;
    // interleaved columns: col = cs + 16*i  (lanes spread across >=16 banks)
    #pragma unroll
    for (int i = 0; i < 8; i++) {
        int col = cs + 16 * i;
        float v;
        if (col < 64) {
            v = 0.f;
            #pragma unroll
            for (int p = 0; p < 8; p++) v += g_Gp[p][r * 64 + col];
        } else {
            v = ((col - 64) == r) ? 1.f : 0.f;
        }
        A[r * 129 + col] = v;
    }
    __syncthreads();
    for (int k = 0; k < 64; k++) {
        float inv = 1.f / A[k * 129 + k];
        float f = A[r * 129 + k];          // read before pivot-row scale
        if (r == k) {
            #pragma unroll
            for (int i = 0; i < 8; i++) A[k * 129 + cs + 16 * i] *= inv;
        }
        __syncthreads();
        if (r != k) {
            #pragma unroll
            for (int i = 0; i < 8; i++) {
                int c = cs + 16 * i;
                A[r * 129 + c] = fmaf(-f, A[k * 129 + c], A[r * 129 + c]);
            }
        }
        __syncthreads();
    }
    // pack g_MP (1024 uint4, one per thread)
    {
        int id = t;
        int lane = id & 31, g = lane >> 2, tq = lane & 3;
        int j = id >> 7, kk = (id >> 5) & 3;
        int n = 8 * j + g, k0 = 16 * kk + 2 * tq;
        float m00 = A[k0 * 129 + 64 + n],       m01 = A[(k0 + 1) * 129 + 64 + n];
        float m10 = A[(k0 + 8) * 129 + 64 + n], m11 = A[(k0 + 9) * 129 + 64 + n];
        uint32_t h0, l0, h1, l1;
        split2(m00, m01, h0, l0);
        split2(m10, m11, h1, l1);
        g_MP[id] = make_uint4(h0, h1, l0, l1);
    }
}

// ---------------- main kernel ----------------
#define SMEM_WORDS 16448
#define SMEM_BYTES (SMEM_WORDS * 4)

__global__ void __launch_bounds__(256, 2)
k_main(const float* __restrict__ hs, float* __restrict__ out) {
    extern __shared__ uint32_t smw[];
    uint4* Bs = (uint4*)smw;

    const int t = threadIdx.x;
    const int wg = t >> 5, lane = t & 31, g = lane >> 2, tq = lane & 3;
    const size_t g0 = (size_t)blockIdx.x * MT;
    const size_t rowA = g0 + 16 * wg + g, rowB = rowA + 8;
    const float* hA = hs + rowA * FD;
    const float* hB = hs + rowB * FD;

    uint32_t sbase = (uint32_t)__cvta_generic_to_shared(smw);

    // prologue: stage GEMM1 B chunk 0 -> buf0
    #pragma unroll
    for (int q = 0; q < 4; q++)
        cpa16(sbase + (t + 256 * q) * 16, g_PP + t + 256 * q);
    CP_COMMIT;

    float acc1[8][4];
    #pragma unroll
    for (int j = 0; j < 8; j++)
        #pragma unroll
        for (int q = 0; q < 4; q++) acc1[j][q] = 0.f;
    float sqA = 0.f, sqB = 0.f;

    float4 pa[4], pb[4];
    #pragma unroll
    for (int kk = 0; kk < 4; kk++) {
        int c0 = 16 * kk + 4 * tq;
        pa[kk] = *(const float4*)(hA + c0);
        pb[kk] = *(const float4*)(hB + c0);
    }

    // ======== GEMM1: acc1 = H * P, K = 1024 (3-term split) ========
    for (int ch = 0; ch < NCH; ch++) {
        CP_WAIT0;
        __syncthreads();
        const int buf = ch & 1;
        if (ch + 1 < NCH) {
            const uint4* src = g_PP + (ch + 1) * 1024;
            #pragma unroll
            for (int q = 0; q < 4; q++)
                cpa16(sbase + (((buf ^ 1) * 1024 + t + 256 * q) * 16), src + t + 256 * q);
            CP_COMMIT;
        }
        uint32_t ah[4][4], al[4][4];
        #pragma unroll
        for (int kk = 0; kk < 4; kk++) {
            float4 a4 = pa[kk], b4 = pb[kk];
            sqA = fmaf(a4.x, a4.x, fmaf(a4.y, a4.y, fmaf(a4.z, a4.z, fmaf(a4.w, a4.w, sqA))));
            sqB = fmaf(b4.x, b4.x, fmaf(b4.y, b4.y, fmaf(b4.z, b4.z, fmaf(b4.w, b4.w, sqB))));
            split2(a4.x, a4.y, ah[kk][0], al[kk][0]);
            split2(b4.x, b4.y, ah[kk][1], al[kk][1]);
            split2(a4.z, a4.w, ah[kk][2], al[kk][2]);
            split2(b4.z, b4.w, ah[kk][3], al[kk][3]);
        }
        if (ch + 1 < NCH) {
            const int cb = (ch + 1) * 64 + 4 * tq;
            #pragma unroll
            for (int kk = 0; kk < 4; kk++) {
                int c0 = cb + 16 * kk;
                pa[kk] = *(const float4*)(hA + c0);
                pb[kk] = *(const float4*)(hB + c0);
            }
        }
        #pragma unroll
        for (int kk = 0; kk < 4; kk++)
            #pragma unroll
            for (int j = 0; j < 8; j += 2) {
                uint4 b0 = Bs[buf * 1024 + (kk * 8 + j) * 32 + lane];
                uint4 b1 = Bs[buf * 1024 + (kk * 8 + j + 1) * 32 + lane];
                mma_bf16(acc1[j],     ah[kk][0], ah[kk][1], ah[kk][2], ah[kk][3], b0.x, b0.y);
                mma_bf16(acc1[j + 1], ah[kk][0], ah[kk][1], ah[kk][2], ah[kk][3], b1.x, b1.y);
                mma_bf16(acc1[j],     ah[kk][0], ah[kk][1], ah[kk][2], ah[kk][3], b0.z, b0.w);
                mma_bf16(acc1[j + 1], ah[kk][0], ah[kk][1], ah[kk][2], ah[kk][3], b1.z, b1.w);
                mma_bf16(acc1[j],     al[kk][0], al[kk][1], al[kk][2], al[kk][3], b0.x, b0.y);
                mma_bf16(acc1[j + 1], al[kk][0], al[kk][1], al[kk][2], al[kk][3], b1.x, b1.y);
            }
    }

    sqA += __shfl_xor_sync(~0u, sqA, 1); sqA += __shfl_xor_sync(~0u, sqA, 2);
    sqB += __shfl_xor_sync(~0u, sqB, 1); sqB += __shfl_xor_sync(~0u, sqB, 2);

    __syncthreads();   // all warps done with GEMM1 Bs

    // prologue: stage GEMM2 P chunk 0 -> buf0 (2048 uint4)
    #pragma unroll
    for (int q = 0; q < 8; q++)
        cpa16(sbase + (t + 256 * q) * 16, g_PT + t + 256 * q);
    CP_COMMIT;

    // ---- repack acc1 (b) into A frags ----
    uint32_t a2h[4][4], a2l[4][4];
    #pragma unroll
    for (int kk = 0; kk < 4; kk++) {
        split2(acc1[2 * kk][0],     acc1[2 * kk][1],     a2h[kk][0], a2l[kk][0]);
        split2(acc1[2 * kk][2],     acc1[2 * kk][3],     a2h[kk][1], a2l[kk][1]);
        split2(acc1[2 * kk + 1][0], acc1[2 * kk + 1][1], a2h[kk][2], a2l[kk][2]);
        split2(acc1[2 * kk + 1][2], acc1[2 * kk + 1][3], a2h[kk][3], a2l[kk][3]);
    }

    // ---- c = b * G^-1 (g_MP, L2-hot); dot = b.c; repack c into A frags ----
    uint32_t a2ch[4][4], a2cl[4][4];
    float dA = 0.f, dB = 0.f;
    #pragma unroll
    for (int jh = 0; jh < 2; jh++) {
        float accd[4][4];
        #pragma unroll
        for (int j = 0; j < 4; j++)
            #pragma unroll
            for (int q = 0; q < 4; q++) accd[j][q] = 0.f;
        #pragma unroll
        for (int kk = 0; kk < 4; kk++)
            #pragma unroll
            for (int j = 0; j < 4; j += 2) {
                uint4 b0 = g_MP[((jh * 4 + j) * 4 + kk) * 32 + lane];
                uint4 b1 = g_MP[((jh * 4 + j + 1) * 4 + kk) * 32 + lane];
                mma_bf16(accd[j],     a2h[kk][0], a2h[kk][1], a2h[kk][2], a2h[kk][3], b0.x, b0.y);
                mma_bf16(accd[j + 1], a2h[kk][0], a2h[kk][1], a2h[kk][2], a2h[kk][3], b1.x, b1.y);
                mma_bf16(accd[j],     a2h[kk][0], a2h[kk][1], a2h[kk][2], a2h[kk][3], b0.z, b0.w);
                mma_bf16(accd[j + 1], a2h[kk][0], a2h[kk][1], a2h[kk][2], a2h[kk][3], b1.z, b1.w);
                mma_bf16(accd[j],     a2l[kk][0], a2l[kk][1], a2l[kk][2], a2l[kk][3], b0.x, b0.y);
                mma_bf16(accd[j + 1], a2l[kk][0], a2l[kk][1], a2l[kk][2], a2l[kk][3], b1.x, b1.y);
            }
        #pragma unroll
        for (int j = 0; j < 4; j++) {
            int jj = jh * 4 + j;
            dA = fmaf(acc1[jj][0], accd[j][0], dA); dA = fmaf(acc1[jj][1], accd[j][1], dA);
            dB = fmaf(acc1[jj][2], accd[j][2], dB); dB = fmaf(acc1[jj][3], accd[j][3], dB);
        }
        split2(accd[0][0], accd[0][1], a2ch[2 * jh][0], a2cl[2 * jh][0]);
        split2(accd[0][2], accd[0][3], a2ch[2 * jh][1], a2cl[2 * jh][1]);
        split2(accd[1][0], accd[1][1], a2ch[2 * jh][2], a2cl[2 * jh][2]);
        split2(accd[1][2], accd[1][3], a2ch[2 * jh][3], a2cl[2 * jh][3]);
        split2(accd[2][0], accd[2][1], a2ch[2 * jh + 1][0], a2cl[2 * jh + 1][0]);
        split2(accd[2][2], accd[2][3], a2ch[2 * jh + 1][1], a2cl[2 * jh + 1][1]);
        split2(accd[3][0], accd[3][1], a2ch[2 * jh + 1][2], a2cl[2 * jh + 1][2]);
        split2(accd[3][2], accd[3][3], a2ch[2 * jh + 1][3], a2cl[2 * jh + 1][3]);
    }
    dA += __shfl_xor_sync(~0u, dA, 1); dA += __shfl_xor_sync(~0u, dA, 2);
    dB += __shfl_xor_sync(~0u, dB, 1); dB += __shfl_xor_sync(~0u, dB, 2);
    const float scA = sqrtf(sqA / fmaxf(sqA - dA, sqA * 1e-12f));
    const float scB = sqrtf(sqB / fmaxf(sqB - dB, sqB * 1e-12f));

    // ======== GEMM2 + fused epilogue: out = (H - c*Pt) * scale ========
    float* pA = out + rowA * FD;
    float* pB = out + rowB * FD;
    const bool fA = ((rowA & 4095) == 0);
    const bool fB = ((rowB & 4095) == 0);

    for (int nc = 0; nc < 8; nc++) {
        CP_WAIT0;
        __syncthreads();
        const int buf = nc & 1;
        if (nc + 1 < 8) {
            const uint4* src = g_PT + (nc + 1) * 2048;
            #pragma unroll
            for (int q = 0; q < 8; q++)
                cpa16(sbase + (((buf ^ 1) * 2048 + t + 256 * q) * 16), src + t + 256 * q);
            CP_COMMIT;
        }
        #pragma unroll
        for (int half = 0; half < 2; half++) {
            float4 hv0[4], hv1[4];
            #pragma unroll
            for (int p = 0; p < 4; p++) {
                int col = nc * 128 + half * 64 + 16 * p + 4 * tq;
                hv0[p] = *(const float4*)(hA + col);
                hv1[p] = *(const float4*)(hB + col);
            }
            float acc2[8][4];
            #pragma unroll
            for (int jl = 0; jl < 8; jl++)
                #pragma unroll
                for (int q = 0; q < 4; q++) acc2[jl][q] = 0.f;
            #pragma unroll
            for (int kk = 0; kk < 4; kk++)
                #pragma unroll
                for (int jl = 0; jl < 8; jl += 2) {
                    uint4 b0 = Bs[buf * 2048 + ((half * 8 + jl) * 4 + kk) * 32 + lane];
                    uint4 b1 = Bs[buf * 2048 + ((half * 8 + jl + 1) * 4 + kk) * 32 + lane];
                    mma_bf16(acc2[jl],     a2ch[kk][0], a2ch[kk][1], a2ch[kk][2], a2ch[kk][3], b0.x, b0.y);
                    mma_bf16(acc2[jl + 1], a2ch[kk][0], a2ch[kk][1], a2ch[kk][2], a2ch[kk][3], b1.x, b1.y);
                    mma_bf16(acc2[jl],     a2ch[kk][0], a2ch[kk][1], a2ch[kk][2], a2ch[kk][3], b0.z, b0.w);
                    mma_bf16(acc2[jl + 1], a2ch[kk][0], a2ch[kk][1], a2ch[kk][2], a2ch[kk][3], b1.z, b1.w);
                    mma_bf16(acc2[jl],     a2cl[kk][0], a2cl[kk][1], a2cl[kk][2], a2cl[kk][3], b0.x, b0.y);
                    mma_bf16(acc2[jl + 1], a2cl[kk][0], a2cl[kk][1], a2cl[kk][2], a2cl[kk][3], b1.x, b1.y);
                }
            #pragma unroll
            for (int p = 0; p < 4; p++) {
                int col = nc * 128 + half * 64 + 16 * p + 4 * tq;
                float4 o0, o1;
                o0.x = (hv0[p].x - acc2[2 * p][0]) * scA;
                o0.y = (hv0[p].y - acc2[2 * p][1]) * scA;
                o0.z = (hv0[p].z - acc2[2 * p + 1][0]) * scA;
                o0.w = (hv0[p].w - acc2[2 * p + 1][1]) * scA;
                o1.x = (hv1[p].x - acc2[2 * p][2]) * scB;
                o1.y = (hv1[p].y - acc2[2 * p][3]) * scB;
                o1.z = (hv1[p].z - acc2[2 * p + 1][2]) * scB;
                o1.w = (hv1[p].w - acc2[2 * p + 1][3]) * scB;
                if (fA) o0 = hv0[p];
                if (fB) o1 = hv1[p];
                __stcs((float4*)(pA + col), o0);
                __stcs((float4*)(pB + col), o1);
            }
        }
    }
}

extern "C" void kernel_launch(void* const* d_in, const int* in_sizes, int n_in,
                              void* d_out, int out_size) {
    const float* hs = (const float*)d_in[0];
    const float* probe = (const float*)d_in[1];
    float* out = (float*)d_out;

    k_prep1<<<64, 256>>>(probe);
    k_inv<<<148, 1024>>>();

    cudaFuncSetAttribute(k_main, cudaFuncAttributeMaxDynamicSharedMemorySize, SMEM_BYTES);
    int rows = in_sizes[0] / FD;            // 32768
    k_main<<<rows / MT, 256, SMEM_BYTES>>>(hs, out);
}

// round 17
// speedup vs baseline: 1.4318x; 1.0044x over previous
#include <cuda_runtime.h>
#include <cstdint>

#define FD 1024
#define RD 64
#define MT 128
#define NCH 16          // GEMM1 chunks of 64 cols

// ---------------- device scratch ----------------
__device__ float g_Gp[8][RD * RD];      // partial Gram matrices
__device__ uint4 g_PP[64 * 8 * 32];     // GEMM1 B frags (P, contraction over f)
__device__ uint4 g_PT[128 * 4 * 32];    // GEMM2 B frags (P, contraction over r, f-permuted)
__device__ uint4 g_MP[8 * 4 * 32];      // d3 B frags (G^-1)
__device__ int   g_cnt;                 // gram-partial completion counter (reset by consumer)

// ---------------- helpers ----------------
__device__ __forceinline__ void split2(float x, float y, uint32_t& hi, uint32_t& lo) {
    asm("cvt.rn.bf16x2.f32 %0, %1, %2;" : "=r"(hi) : "f"(y), "f"(x));
    float xr = x - __uint_as_float(hi << 16);
    float yr = y - __uint_as_float(hi & 0xffff0000u);
    asm("cvt.rn.bf16x2.f32 %0, %1, %2;" : "=r"(lo) : "f"(yr), "f"(xr));
}

__device__ __forceinline__ void mma_bf16(float* d,
    uint32_t a0, uint32_t a1, uint32_t a2, uint32_t a3,
    uint32_t b0, uint32_t b1) {
    asm volatile("mma.sync.aligned.m16n8k16.row.col.f32.bf16.bf16.f32 "
        "{%0,%1,%2,%3}, {%4,%5,%6,%7}, {%8,%9}, {%0,%1,%2,%3};"
        : "+f"(d[0]), "+f"(d[1]), "+f"(d[2]), "+f"(d[3])
        : "r"(a0), "r"(a1), "r"(a2), "r"(a3), "r"(b0), "r"(b1));
}

__device__ __forceinline__ void cpa16(uint32_t s, const void* g) {
    asm volatile("cp.async.cg.shared.global [%0], [%1], 16;" :: "r"(s), "l"(g));
}
#define CP_COMMIT asm volatile("cp.async.commit_group;" ::: "memory")
#define CP_WAIT0  asm volatile("cp.async.wait_group 0;" ::: "memory")

// ---------------- single fused prep kernel: grid 64 x 1024 ----------------
// blocks 0..15 : pack g_PP        (block 0 additionally: spin for gram, GJ, pack g_MP)
// blocks 16..31: pack g_PT
// blocks 32..39: gram partial (c = b-32), signal counter
__global__ void __launch_bounds__(1024, 1)
k_prep(const float* __restrict__ probe) {
    __shared__ float S[128 * 68];          // 34.8 KB: gram tile (128x68) OR GJ matrix (64x129)
    const int t = threadIdx.x;
    const int b = blockIdx.x;

    if (b < 16) {
        // ---- pack g_PP ----
        int id = b * 1024 + t;
        int lane = id & 31, g = lane >> 2, tq = lane & 3;
        int kk = id >> 8, j = (id >> 5) & 7;
        int n = 8 * j + g, k0 = 16 * kk + 4 * tq;
        float p00 = probe[(k0) * 64 + n],     p01 = probe[(k0 + 1) * 64 + n];
        float p10 = probe[(k0 + 2) * 64 + n], p11 = probe[(k0 + 3) * 64 + n];
        uint32_t h0, l0, h1, l1;
        split2(p00, p01, h0, l0);
        split2(p10, p11, h1, l1);
        g_PP[id] = make_uint4(h0, h1, l0, l1);
    } else if (b < 32) {
        // ---- pack g_PT ----
        int id = (b - 16) * 1024 + t;
        int lane = id & 31, g = lane >> 2, tq = lane & 3;
        int T = id >> 7, kk = (id >> 5) & 3;
        int f = 16 * (T >> 1) + 4 * (g >> 1) + 2 * (T & 1) + (g & 1);
        int r0 = 16 * kk + 2 * tq;
        float w00 = probe[f * 64 + r0],     w01 = probe[f * 64 + r0 + 1];
        float w10 = probe[f * 64 + r0 + 8], w11 = probe[f * 64 + r0 + 9];
        uint32_t h0, l0, h1, l1;
        split2(w00, w01, h0, l0);
        split2(w10, w11, h1, l1);
        g_PT[id] = make_uint4(h0, h1, l0, l1);
    } else if (b < 40) {
        // ---- gram partial over f-rows [c*128, c*128+128) ----
        const int c = b - 32;
        float* Ps = S;                     // [128][68] -- stride 68 = 272 B (16 B multiple)
        {
            const float4* src = (const float4*)(probe + c * 128 * 64);
            #pragma unroll
            for (int i = 0; i < 2; i++) {
                int idx = t + 1024 * i;    // 2048 float4 total
                int fl = idx >> 4, r4 = (idx & 15) << 2;
                float4 v = src[idx];
                *(float4*)(Ps + fl * 68 + r4) = v;
            }
        }
        __syncthreads();
        const int i0 = (t >> 5) * 2, j0 = (t & 31) * 2;
        float a00 = 0.f, a01 = 0.f, a10 = 0.f, a11 = 0.f;
        #pragma unroll 8
        for (int k = 0; k < 128; k++) {
            float2 av = *(const float2*)(Ps + k * 68 + i0);
            float2 bv = *(const float2*)(Ps + k * 68 + j0);
            a00 = fmaf(av.x, bv.x, a00); a01 = fmaf(av.x, bv.y, a01);
            a10 = fmaf(av.y, bv.x, a10); a11 = fmaf(av.y, bv.y, a11);
        }
        g_Gp[c][(i0) * 64 + j0]     = a00;
        g_Gp[c][(i0) * 64 + j0 + 1] = a01;
        g_Gp[c][(i0 + 1) * 64 + j0]     = a10;
        g_Gp[c][(i0 + 1) * 64 + j0 + 1] = a11;
        __threadfence();
        __syncthreads();
        if (t == 0) atomicAdd(&g_cnt, 1);
    }

    // ---- block 0: wait for all gram partials, then GJ + MP pack ----
    if (b == 0) {
        if (t == 0) { while (atomicAdd(&g_cnt, 0) < 8) __nanosleep(32); }
        __syncthreads();
        float* A = S;                      // [64][129]
        const int r = t >> 4, cs = t & 15;
        #pragma unroll
        for (int i = 0; i < 8; i++) {
            int col = cs + 16 * i;
            float v;
            if (col < 64) {
                v = 0.f;
                #pragma unroll
                for (int p = 0; p < 8; p++) v += g_Gp[p][r * 64 + col];
            } else {
                v = ((col - 64) == r) ? 1.f : 0.f;
            }
            A[r * 129 + col] = v;
        }
        __syncthreads();
        for (int k = 0; k < 64; k++) {
            float inv = 1.f / A[k * 129 + k];
            float f = A[r * 129 + k];
            if (r == k) {
                #pragma unroll
                for (int i = 0; i < 8; i++) A[k * 129 + cs + 16 * i] *= inv;
            }
            __syncthreads();
            if (r != k) {
                #pragma unroll
                for (int i = 0; i < 8; i++) {
                    int c2 = cs + 16 * i;
                    A[r * 129 + c2] = fmaf(-f, A[k * 129 + c2], A[r * 129 + c2]);
                }
            }
            __syncthreads();
        }
        {
            int id = t;
            int lane = id & 31, g = lane >> 2, tq = lane & 3;
            int j = id >> 7, kk = (id >> 5) & 3;
            int n = 8 * j + g, k0 = 16 * kk + 2 * tq;
            float m00 = A[k0 * 129 + 64 + n],       m01 = A[(k0 + 1) * 129 + 64 + n];
            float m10 = A[(k0 + 8) * 129 + 64 + n], m11 = A[(k0 + 9) * 129 + 64 + n];
            uint32_t h0, l0, h1, l1;
            split2(m00, m01, h0, l0);
            split2(m10, m11, h1, l1);
            g_MP[id] = make_uint4(h0, h1, l0, l1);
        }
        __syncthreads();
        if (t == 0) atomicExch(&g_cnt, 0);   // reset for next graph replay
    }
}

// ---------------- main kernel ----------------
#define SMEM_WORDS 16448
#define SMEM_BYTES (SMEM_WORDS * 4)

__global__ void __launch_bounds__(256, 2)
k_main(const float* __restrict__ hs, float* __restrict__ out) {
    extern __shared__ uint32_t smw[];
    uint4* Bs = (uint4*)smw;

    const int t = threadIdx.x;
    const int wg = t >> 5, lane = t & 31, g = lane >> 2, tq = lane & 3;
    const size_t g0 = (size_t)blockIdx.x * MT;
    const size_t rowA = g0 + 16 * wg + g, rowB = rowA + 8;
    const float* hA = hs + rowA * FD;
    const float* hB = hs + rowB * FD;

    uint32_t sbase = (uint32_t)__cvta_generic_to_shared(smw);

    // prologue: stage GEMM1 B chunk 0 -> buf0
    #pragma unroll
    for (int q = 0; q < 4; q++)
        cpa16(sbase + (t + 256 * q) * 16, g_PP + t + 256 * q);
    CP_COMMIT;

    float acc1[8][4];
    #pragma unroll
    for (int j = 0; j < 8; j++)
        #pragma unroll
        for (int q = 0; q < 4; q++) acc1[j][q] = 0.f;
    float sqA = 0.f, sqB = 0.f;

    float4 pa[4], pb[4];
    #pragma unroll
    for (int kk = 0; kk < 4; kk++) {
        int c0 = 16 * kk + 4 * tq;
        pa[kk] = *(const float4*)(hA + c0);
        pb[kk] = *(const float4*)(hB + c0);
    }

    // ======== GEMM1: acc1 = H * P, K = 1024 (3-term split) ========
    for (int ch = 0; ch < NCH; ch++) {
        CP_WAIT0;
        __syncthreads();
        const int buf = ch & 1;
        if (ch + 1 < NCH) {
            const uint4* src = g_PP + (ch + 1) * 1024;
            #pragma unroll
            for (int q = 0; q < 4; q++)
                cpa16(sbase + (((buf ^ 1) * 1024 + t + 256 * q) * 16), src + t + 256 * q);
            CP_COMMIT;
        }
        uint32_t ah[4][4], al[4][4];
        #pragma unroll
        for (int kk = 0; kk < 4; kk++) {
            float4 a4 = pa[kk], b4 = pb[kk];
            sqA = fmaf(a4.x, a4.x, fmaf(a4.y, a4.y, fmaf(a4.z, a4.z, fmaf(a4.w, a4.w, sqA))));
            sqB = fmaf(b4.x, b4.x, fmaf(b4.y, b4.y, fmaf(b4.z, b4.z, fmaf(b4.w, b4.w, sqB))));
            split2(a4.x, a4.y, ah[kk][0], al[kk][0]);
            split2(b4.x, b4.y, ah[kk][1], al[kk][1]);
            split2(a4.z, a4.w, ah[kk][2], al[kk][2]);
            split2(b4.z, b4.w, ah[kk][3], al[kk][3]);
        }
        if (ch + 1 < NCH) {
            const int cb = (ch + 1) * 64 + 4 * tq;
            #pragma unroll
            for (int kk = 0; kk < 4; kk++) {
                int c0 = cb + 16 * kk;
                pa[kk] = *(const float4*)(hA + c0);
                pb[kk] = *(const float4*)(hB + c0);
            }
        }
        #pragma unroll
        for (int kk = 0; kk < 4; kk++)
            #pragma unroll
            for (int j = 0; j < 8; j += 2) {
                uint4 b0 = Bs[buf * 1024 + (kk * 8 + j) * 32 + lane];
                uint4 b1 = Bs[buf * 1024 + (kk * 8 + j + 1) * 32 + lane];
                mma_bf16(acc1[j],     ah[kk][0], ah[kk][1], ah[kk][2], ah[kk][3], b0.x, b0.y);
                mma_bf16(acc1[j + 1], ah[kk][0], ah[kk][1], ah[kk][2], ah[kk][3], b1.x, b1.y);
                mma_bf16(acc1[j],     ah[kk][0], ah[kk][1], ah[kk][2], ah[kk][3], b0.z, b0.w);
                mma_bf16(acc1[j + 1], ah[kk][0], ah[kk][1], ah[kk][2], ah[kk][3], b1.z, b1.w);
                mma_bf16(acc1[j],     al[kk][0], al[kk][1], al[kk][2], al[kk][3], b0.x, b0.y);
                mma_bf16(acc1[j + 1], al[kk][0], al[kk][1], al[kk][2], al[kk][3], b1.x, b1.y);
            }
    }

    sqA += __shfl_xor_sync(~0u, sqA, 1); sqA += __shfl_xor_sync(~0u, sqA, 2);
    sqB += __shfl_xor_sync(~0u, sqB, 1); sqB += __shfl_xor_sync(~0u, sqB, 2);

    __syncthreads();   // all warps done with GEMM1 Bs

    // prologue: stage GEMM2 P chunk 0 -> buf0 (2048 uint4)
    #pragma unroll
    for (int q = 0; q < 8; q++)
        cpa16(sbase + (t + 256 * q) * 16, g_PT + t + 256 * q);
    CP_COMMIT;

    // ---- repack acc1 (b) into A frags ----
    uint32_t a2h[4][4], a2l[4][4];
    #pragma unroll
    for (int kk = 0; kk < 4; kk++) {
        split2(acc1[2 * kk][0],     acc1[2 * kk][1],     a2h[kk][0], a2l[kk][0]);
        split2(acc1[2 * kk][2],     acc1[2 * kk][3],     a2h[kk][1], a2l[kk][1]);
        split2(acc1[2 * kk + 1][0], acc1[2 * kk + 1][1], a2h[kk][2], a2l[kk][2]);
        split2(acc1[2 * kk + 1][2], acc1[2 * kk + 1][3], a2h[kk][3], a2l[kk][3]);
    }

    // ---- c = b * G^-1 (g_MP, L2-hot); dot = b.c; repack c into A frags ----
    uint32_t a2ch[4][4], a2cl[4][4];
    float dA = 0.f, dB = 0.f;
    #pragma unroll
    for (int jh = 0; jh < 2; jh++) {
        float accd[4][4];
        #pragma unroll
        for (int j = 0; j < 4; j++)
            #pragma unroll
            for (int q = 0; q < 4; q++) accd[j][q] = 0.f;
        #pragma unroll
        for (int kk = 0; kk < 4; kk++)
            #pragma unroll
            for (int j = 0; j < 4; j += 2) {
                uint4 b0 = g_MP[((jh * 4 + j) * 4 + kk) * 32 + lane];
                uint4 b1 = g_MP[((jh * 4 + j + 1) * 4 + kk) * 32 + lane];
                mma_bf16(accd[j],     a2h[kk][0], a2h[kk][1], a2h[kk][2], a2h[kk][3], b0.x, b0.y);
                mma_bf16(accd[j + 1], a2h[kk][0], a2h[kk][1], a2h[kk][2], a2h[kk][3], b1.x, b1.y);
                mma_bf16(accd[j],     a2h[kk][0], a2h[kk][1], a2h[kk][2], a2h[kk][3], b0.z, b0.w);
                mma_bf16(accd[j + 1], a2h[kk][0], a2h[kk][1], a2h[kk][2], a2h[kk][3], b1.z, b1.w);
                mma_bf16(accd[j],     a2l[kk][0], a2l[kk][1], a2l[kk][2], a2l[kk][3], b0.x, b0.y);
                mma_bf16(accd[j + 1], a2l[kk][0], a2l[kk][1], a2l[kk][2], a2l[kk][3], b1.x, b1.y);
            }
        #pragma unroll
        for (int j = 0; j < 4; j++) {
            int jj = jh * 4 + j;
            dA = fmaf(acc1[jj][0], accd[j][0], dA); dA = fmaf(acc1[jj][1], accd[j][1], dA);
            dB = fmaf(acc1[jj][2], accd[j][2], dB); dB = fmaf(acc1[jj][3], accd[j][3], dB);
        }
        split2(accd[0][0], accd[0][1], a2ch[2 * jh][0], a2cl[2 * jh][0]);
        split2(accd[0][2], accd[0][3], a2ch[2 * jh][1], a2cl[2 * jh][1]);
        split2(accd[1][0], accd[1][1], a2ch[2 * jh][2], a2cl[2 * jh][2]);
        split2(accd[1][2], accd[1][3], a2ch[2 * jh][3], a2cl[2 * jh][3]);
        split2(accd[2][0], accd[2][1], a2ch[2 * jh + 1][0], a2cl[2 * jh + 1][0]);
        split2(accd[2][2], accd[2][3], a2ch[2 * jh + 1][1], a2cl[2 * jh + 1][1]);
        split2(accd[3][0], accd[3][1], a2ch[2 * jh + 1][2], a2cl[2 * jh + 1][2]);
        split2(accd[3][2], accd[3][3], a2ch[2 * jh + 1][3], a2cl[2 * jh + 1][3]);
    }
    dA += __shfl_xor_sync(~0u, dA, 1); dA += __shfl_xor_sync(~0u, dA, 2);
    dB += __shfl_xor_sync(~0u, dB, 1); dB += __shfl_xor_sync(~0u, dB, 2);
    const float scA = sqrtf(sqA / fmaxf(sqA - dA, sqA * 1e-12f));
    const float scB = sqrtf(sqB / fmaxf(sqB - dB, sqB * 1e-12f));

    // ======== GEMM2 + fused epilogue: out = (H - c*Pt) * scale ========
    float* pA = out + rowA * FD;
    float* pB = out + rowB * FD;
    const bool fA = ((rowA & 4095) == 0);
    const bool fB = ((rowB & 4095) == 0);

    for (int nc = 0; nc < 8; nc++) {
        CP_WAIT0;
        __syncthreads();
        const int buf = nc & 1;
        if (nc + 1 < 8) {
            const uint4* src = g_PT + (nc + 1) * 2048;
            #pragma unroll
            for (int q = 0; q < 8; q++)
                cpa16(sbase + (((buf ^ 1) * 2048 + t + 256 * q) * 16), src + t + 256 * q);
            CP_COMMIT;
        }
        #pragma unroll
        for (int half = 0; half < 2; half++) {
            float4 hv0[4], hv1[4];
            #pragma unroll
            for (int p = 0; p < 4; p++) {
                int col = nc * 128 + half * 64 + 16 * p + 4 * tq;
                hv0[p] = *(const float4*)(hA + col);
                hv1[p] = *(const float4*)(hB + col);
            }
            float acc2[8][4];
            #pragma unroll
            for (int jl = 0; jl < 8; jl++)
                #pragma unroll
                for (int q = 0; q < 4; q++) acc2[jl][q] = 0.f;
            #pragma unroll
            for (int kk = 0; kk < 4; kk++)
                #pragma unroll
                for (int jl = 0; jl < 8; jl += 2) {
                    uint4 b0 = Bs[buf * 2048 + ((half * 8 + jl) * 4 + kk) * 32 + lane];
                    uint4 b1 = Bs[buf * 2048 + ((half * 8 + jl + 1) * 4 + kk) * 32 + lane];
                    mma_bf16(acc2[jl],     a2ch[kk][0], a2ch[kk][1], a2ch[kk][2], a2ch[kk][3], b0.x, b0.y);
                    mma_bf16(acc2[jl + 1], a2ch[kk][0], a2ch[kk][1], a2ch[kk][2], a2ch[kk][3], b1.x, b1.y);
                    mma_bf16(acc2[jl],     a2ch[kk][0], a2ch[kk][1], a2ch[kk][2], a2ch[kk][3], b0.z, b0.w);
                    mma_bf16(acc2[jl + 1], a2ch[kk][0], a2ch[kk][1], a2ch[kk][2], a2ch[kk][3], b1.z, b1.w);
                    mma_bf16(acc2[jl],     a2cl[kk][0], a2cl[kk][1], a2cl[kk][2], a2cl[kk][3], b0.x, b0.y);
                    mma_bf16(acc2[jl + 1], a2cl[kk][0], a2cl[kk][1], a2cl[kk][2], a2cl[kk][3], b1.x, b1.y);
                }
            #pragma unroll
            for (int p = 0; p < 4; p++) {
                int col = nc * 128 + half * 64 + 16 * p + 4 * tq;
                float4 o0, o1;
                o0.x = (hv0[p].x - acc2[2 * p][0]) * scA;
                o0.y = (hv0[p].y - acc2[2 * p][1]) * scA;
                o0.z = (hv0[p].z - acc2[2 * p + 1][0]) * scA;
                o0.w = (hv0[p].w - acc2[2 * p + 1][1]) * scA;
                o1.x = (hv1[p].x - acc2[2 * p][2]) * scB;
                o1.y = (hv1[p].y - acc2[2 * p][3]) * scB;
                o1.z = (hv1[p].z - acc2[2 * p + 1][2]) * scB;
                o1.w = (hv1[p].w - acc2[2 * p + 1][3]) * scB;
                if (fA) o0 = hv0[p];
                if (fB) o1 = hv1[p];
                __stcs((float4*)(pA + col), o0);
                __stcs((float4*)(pB + col), o1);
            }
        }
    }
}

extern "C" void kernel_launch(void* const* d_in, const int* in_sizes, int n_in,
                              void* d_out, int out_size) {
    const float* hs = (const float*)d_in[0];
    const float* probe = (const float*)d_in[1];
    float* out = (float*)d_out;

    k_prep<<<64, 1024>>>(probe);

    cudaFuncSetAttribute(k_main, cudaFuncAttributeMaxDynamicSharedMemorySize, SMEM_BYTES);
    int rows = in_sizes[0] / FD;            // 32768
    k_main<<<rows / MT, 256, SMEM_BYTES>>>(hs, out);
}